// round 2
// baseline (speedup 1.0000x reference)
#include <cuda_runtime.h>

// SSIM over 128 independent 384x384 fp32 image pairs, 7x7 VALID box filter,
// skimage sample-covariance correction, global mean -> scalar.
//
// v2: software-pipelined global loads (prefetch next 2 input rows into
// registers before the barrier+horizontal phase) and 2 output rows per
// barrier pair (Vs[2][5][384]) -> 1 barrier/row instead of 2, and better
// thread utilization in the horizontal phase.

#define WINR   7
#define IMG_H  384
#define IMG_W  384
#define OUT_W  378          // IMG_W - 6
#define OUT_H  378
#define NIMG   128          // 32 * 4
#define BANDS  4
#define BAND_ROWS 96        // bands: 96,96,96,90 (all even)
#define NTHREADS 256
#define NPAIRS (OUT_W / 2)  // 189
#define ITEMS  (2 * NPAIRS) // 378 horizontal work items per 2-row batch

__device__ float g_partials[NIMG * BANDS];

__global__ __launch_bounds__(NTHREADS, 4)
void ssim_band_kernel(const float* __restrict__ pred,
                      const float* __restrict__ actual) {
    const int img  = blockIdx.y;
    const int band = blockIdx.x;
    const int ob = band * BAND_ROWS;
    const int oe = min(ob + BAND_ROWS, OUT_H);

    __shared__ __align__(16) float ringX[WINR][IMG_W];
    __shared__ __align__(16) float ringY[WINR][IMG_W];
    __shared__ __align__(16) float Vs[2][5][IMG_W];
    __shared__ float red[NTHREADS];

    const float* __restrict__ xim = pred   + (size_t)img * IMG_H * IMG_W;
    const float* __restrict__ yim = actual + (size_t)img * IMG_H * IMG_W;

    const int t  = threadIdx.x;
    const int c0 = t;
    const int c1 = t + NTHREADS;            // valid if t < 128
    const bool has2 = (c1 < IMG_W);

    // running vertical sums for the two owned columns
    float sx0=0.f, sy0=0.f, sxx0=0.f, syy0=0.f, sxy0=0.f;
    float sx1=0.f, sy1=0.f, sxx1=0.f, syy1=0.f, sxy1=0.f;

    // ---- prologue: rows ob .. ob+5 into sums + ring ----
    #pragma unroll 1
    for (int r = ob; r < ob + 6; ++r) {
        const int s = r % WINR;
        float x = xim[r * IMG_W + c0];
        float y = yim[r * IMG_W + c0];
        ringX[s][c0] = x; ringY[s][c0] = y;
        sx0 += x; sy0 += y; sxx0 += x*x; syy0 += y*y; sxy0 += x*y;
        if (has2) {
            float x2 = xim[r * IMG_W + c1];
            float y2 = yim[r * IMG_W + c1];
            ringX[s][c1] = x2; ringY[s][c1] = y2;
            sx1 += x2; sy1 += y2; sxx1 += x2*x2; syy1 += y2*y2; sxy1 += x2*y2;
        }
    }

    // ---- prefetch rows ob+6, ob+7 (consumed by first iteration) ----
    float pAx0, pAy0, pAx1, pAy1;   // row r+6
    float pBx0, pBy0, pBx1, pBy1;   // row r+7
    {
        int rA = ob + 6, rB = ob + 7;
        pAx0 = xim[rA * IMG_W + c0];  pAy0 = yim[rA * IMG_W + c0];
        pBx0 = xim[rB * IMG_W + c0];  pBy0 = yim[rB * IMG_W + c0];
        if (has2) {
            pAx1 = xim[rA * IMG_W + c1];  pAy1 = yim[rA * IMG_W + c1];
            pBx1 = xim[rB * IMG_W + c1];  pBy1 = yim[rB * IMG_W + c1];
        } else { pAx1 = pAy1 = pBx1 = pBy1 = 0.f; }
    }

    const float inv_np = 1.0f / 49.0f;
    const float covn   = 49.0f / 48.0f;
    const float C1v    = 0.01f * 0.01f;
    const float C2v    = 0.03f * 0.03f;

    float acc = 0.0f;

    // ---- main loop: 2 output rows per iteration ----
    #pragma unroll 1
    for (int r = ob; r < oe; r += 2) {
        // ===== output row r : window rows [r, r+6] =====
        if (r > ob) {
            const int s = (r - 1) % WINR;         // row leaving: r-1
            float x = ringX[s][c0], y = ringY[s][c0];
            sx0 -= x; sy0 -= y; sxx0 -= x*x; syy0 -= y*y; sxy0 -= x*y;
            if (has2) {
                float x2 = ringX[s][c1], y2 = ringY[s][c1];
                sx1 -= x2; sy1 -= y2; sxx1 -= x2*x2; syy1 -= y2*y2; sxy1 -= x2*y2;
            }
        }
        {
            const int s = (r + 6) % WINR;         // row entering: r+6 (prefetched)
            ringX[s][c0] = pAx0; ringY[s][c0] = pAy0;
            sx0 += pAx0; sy0 += pAy0; sxx0 += pAx0*pAx0; syy0 += pAy0*pAy0; sxy0 += pAx0*pAy0;
            if (has2) {
                ringX[s][c1] = pAx1; ringY[s][c1] = pAy1;
                sx1 += pAx1; sy1 += pAy1; sxx1 += pAx1*pAx1; syy1 += pAy1*pAy1; sxy1 += pAx1*pAy1;
            }
        }
        Vs[0][0][c0]=sx0; Vs[0][1][c0]=sy0; Vs[0][2][c0]=sxx0; Vs[0][3][c0]=syy0; Vs[0][4][c0]=sxy0;
        if (has2) { Vs[0][0][c1]=sx1; Vs[0][1][c1]=sy1; Vs[0][2][c1]=sxx1; Vs[0][3][c1]=syy1; Vs[0][4][c1]=sxy1; }

        // ===== output row r+1 : window rows [r+1, r+7] =====
        {
            const int s = r % WINR;               // row leaving: r
            float x = ringX[s][c0], y = ringY[s][c0];
            sx0 -= x; sy0 -= y; sxx0 -= x*x; syy0 -= y*y; sxy0 -= x*y;
            if (has2) {
                float x2 = ringX[s][c1], y2 = ringY[s][c1];
                sx1 -= x2; sy1 -= y2; sxx1 -= x2*x2; syy1 -= y2*y2; sxy1 -= x2*y2;
            }
        }
        {
            const int s = (r + 7) % WINR;         // row entering: r+7 (prefetched)
            ringX[s][c0] = pBx0; ringY[s][c0] = pBy0;
            sx0 += pBx0; sy0 += pBy0; sxx0 += pBx0*pBx0; syy0 += pBy0*pBy0; sxy0 += pBx0*pBy0;
            if (has2) {
                ringX[s][c1] = pBx1; ringY[s][c1] = pBy1;
                sx1 += pBx1; sy1 += pBy1; sxx1 += pBx1*pBx1; syy1 += pBy1*pBy1; sxy1 += pBx1*pBy1;
            }
        }
        Vs[1][0][c0]=sx0; Vs[1][1][c0]=sy0; Vs[1][2][c0]=sxx0; Vs[1][3][c0]=syy0; Vs[1][4][c0]=sxy0;
        if (has2) { Vs[1][0][c1]=sx1; Vs[1][1][c1]=sy1; Vs[1][2][c1]=sxx1; Vs[1][3][c1]=syy1; Vs[1][4][c1]=sxy1; }

        // ===== prefetch rows r+8, r+9 for next iteration (clamped; no OOB) =====
        {
            int rA = r + 8, rB = r + 9;
            if (rA > IMG_H - 1) rA = IMG_H - 1;
            if (rB > IMG_H - 1) rB = IMG_H - 1;
            pAx0 = xim[rA * IMG_W + c0];  pAy0 = yim[rA * IMG_W + c0];
            pBx0 = xim[rB * IMG_W + c0];  pBy0 = yim[rB * IMG_W + c0];
            if (has2) {
                pAx1 = xim[rA * IMG_W + c1];  pAy1 = yim[rA * IMG_W + c1];
                pBx1 = xim[rB * IMG_W + c1];  pBy1 = yim[rB * IMG_W + c1];
            }
        }

        __syncthreads();

        // ===== horizontal phase: 378 items (2 rows x 189 pairs) =====
        #pragma unroll
        for (int base = 0; base < ITEMS; base += NTHREADS) {
            const int item = base + t;
            if (item < ITEMS) {
                const int rr = (item >= NPAIRS) ? 1 : 0;
                const int o  = (item - rr * NPAIRS) * 2;
                float w0[5], w1[5];
                #pragma unroll
                for (int q = 0; q < 5; ++q) {
                    const float2* vq = reinterpret_cast<const float2*>(&Vs[rr][q][o]);
                    float2 p0 = vq[0];
                    float2 p1 = vq[1];
                    float2 p2 = vq[2];
                    float2 p3 = vq[3];
                    float s6 = p0.y + p1.x + p1.y + p2.x + p2.y + p3.x;
                    w0[q] = s6 + p0.x;
                    w1[q] = s6 + p3.y;
                }
                #pragma unroll
                for (int which = 0; which < 2; ++which) {
                    const float* w = which ? w1 : w0;
                    float ux  = w[0] * inv_np;
                    float uy  = w[1] * inv_np;
                    float uxx = w[2] * inv_np;
                    float uyy = w[3] * inv_np;
                    float uxy = w[4] * inv_np;
                    float vx  = covn * (uxx - ux * ux);
                    float vy  = covn * (uyy - uy * uy);
                    float vxy = covn * (uxy - ux * uy);
                    float num = (2.0f * ux * uy + C1v) * (2.0f * vxy + C2v);
                    float den = (ux * ux + uy * uy + C1v) * (vx + vy + C2v);
                    acc += __fdividef(num, den);
                }
            }
        }
        __syncthreads();   // protect Vs before next batch overwrites it
    }

    // deterministic block reduction
    red[t] = acc;
    __syncthreads();
    #pragma unroll
    for (int s = NTHREADS / 2; s > 0; s >>= 1) {
        if (t < s) red[t] += red[t + s];
        __syncthreads();
    }
    if (t == 0) g_partials[img * BANDS + band] = red[0];
}

__global__ void ssim_reduce_kernel(float* __restrict__ out) {
    __shared__ float red[NIMG * BANDS];
    const int t = threadIdx.x;
    red[t] = g_partials[t];
    __syncthreads();
    #pragma unroll
    for (int s = (NIMG * BANDS) / 2; s > 0; s >>= 1) {
        if (t < s) red[t] += red[t + s];
        __syncthreads();
    }
    if (t == 0) {
        out[0] = red[0] * (1.0f / ((float)NIMG * (float)OUT_W * (float)OUT_H));
    }
}

extern "C" void kernel_launch(void* const* d_in, const int* in_sizes, int n_in,
                              void* d_out, int out_size) {
    const float* pred   = (const float*)d_in[0];
    const float* actual = (const float*)d_in[1];
    float* out = (float*)d_out;

    dim3 grid(BANDS, NIMG);
    ssim_band_kernel<<<grid, NTHREADS>>>(pred, actual);
    ssim_reduce_kernel<<<1, NIMG * BANDS>>>(out);
}

// round 3
// speedup vs baseline: 1.2105x; 1.2105x over previous
#include <cuda_runtime.h>

// SSIM, 7x7 VALID box, 128 x 384x384 fp32 pairs -> scalar mean.
//
// v3: barrier-free, shared-memory-free warp-strip design.
// Each warp owns a 26-wide output column strip x 189-row band of one image.
// Lane l holds input column (base+l). Vertical 7-row sliding sums of
// {x, y, x^2, y^2, xy} kept in registers (history ring static via unroll-7).
// Horizontal 7-sum across lanes via 4 shuffles + 4 adds per quantity.
// Per-warp partials -> deterministic final reduce kernel.

#define IMG_H   384
#define IMG_W   384
#define OUT_W   378
#define OUT_H   378
#define NIMG    128
#define STRIPS  15          // ceil(378/26); strip 14 clamped
#define RBANDS  2           // 378 = 2 * 189; 189 = 27 * 7
#define ROWS_PER_BAND 189
#define WARPS_TOTAL (NIMG * STRIPS * RBANDS)   // 3840
#define WARPS_PER_CTA 8
#define NCTA (WARPS_TOTAL / WARPS_PER_CTA)     // 480
#define NPART WARPS_TOTAL

__device__ float g_partials[NPART];

__global__ __launch_bounds__(WARPS_PER_CTA * 32)
void ssim_warp_kernel(const float* __restrict__ pred,
                      const float* __restrict__ actual) {
    const int gtid = blockIdx.x * blockDim.x + threadIdx.x;
    const int W    = gtid >> 5;          // global warp id
    const int lane = gtid & 31;

    // W -> (img, band, strip)
    const int img   = W / (STRIPS * RBANDS);
    const int rem   = W - img * (STRIPS * RBANDS);
    const int band  = rem / STRIPS;
    const int strip = rem - band * STRIPS;

    const int base  = (strip == STRIPS - 1) ? (OUT_W - 26) : (strip * 26); // <=352
    const int c     = base + lane;                       // input column, <=383
    const int r0in  = band * ROWS_PER_BAND;              // first input row

    // valid output lanes: ocol in [strip*26, min(strip*26+26, OUT_W)), lane<26
    const int ocol       = base + lane;
    const int strip_lo   = strip * 26;
    const int strip_hi   = min(strip_lo + 26, OUT_W);
    const bool valid     = (lane < 26) && (ocol >= strip_lo) && (ocol < strip_hi);
    const float vmask    = valid ? 1.0f : 0.0f;

    const float* __restrict__ xcol = pred   + (size_t)img * IMG_H * IMG_W + c;
    const float* __restrict__ ycol = actual + (size_t)img * IMG_H * IMG_W + c;

    // history ring (static indices via unroll-7) and running column sums
    float hx[7], hy[7];
    float sx = 0.f, sy = 0.f, sxx = 0.f, syy = 0.f, sxy = 0.f;

    #pragma unroll
    for (int k = 0; k < 6; ++k) {
        float x = xcol[(size_t)(r0in + k) * IMG_W];
        float y = ycol[(size_t)(r0in + k) * IMG_W];
        hx[k] = x; hy[k] = y;
        sx += x; sy += y;
        sxx = fmaf(x, x, sxx); syy = fmaf(y, y, syy); sxy = fmaf(x, y, sxy);
    }
    hx[6] = 0.f; hy[6] = 0.f;

    // prefetch row r0in+6 (consumed by output row 0)
    float cx = xcol[(size_t)(r0in + 6) * IMG_W];
    float cy = ycol[(size_t)(r0in + 6) * IMG_W];

    const float s1   = 1.0f / 49.0f;
    const float covn = 49.0f / 48.0f;
    const float C1v  = 0.01f * 0.01f;
    const float C2v  = 0.03f * 0.03f;
    const float k_n1 = 2.0f * s1 * s1;        // for 2*ux*uy
    const float k_s2 = s1 * s1;               // for ux^2+uy^2
    const float k_cv = covn * s1;             // for variance terms
    const float k_c2 = 2.0f * covn * s1;      // for 2*vxy

    float acc = 0.0f;

    #pragma unroll 1
    for (int base7 = 0; base7 < ROWS_PER_BAND; base7 += 7) {
        #pragma unroll
        for (int j = 0; j < 7; ++j) {
            const int slot = (j + 6) % 7;      // compile-time constant
            // retire the row leaving the window (slot holds it; 0 on 1st iter)
            {
                float ox = hx[slot], oy = hy[slot];
                sx -= ox; sy -= oy;
                sxx = fmaf(-ox, ox, sxx); syy = fmaf(-oy, oy, syy);
                sxy = fmaf(-ox, oy, sxy);
            }
            // admit prefetched row (out_k + 6)
            hx[slot] = cx; hy[slot] = cy;
            sx += cx; sy += cy;
            sxx = fmaf(cx, cx, sxx); syy = fmaf(cy, cy, syy);
            sxy = fmaf(cx, cy, sxy);

            // prefetch next input row (out_k + 7), clamped
            {
                int nr = base7 + j + 7;
                if (nr > ROWS_PER_BAND + 5) nr = ROWS_PER_BAND + 5;
                cx = xcol[(size_t)(r0in + nr) * IMG_W];
                cy = ycol[(size_t)(r0in + nr) * IMG_W];
            }

            // horizontal 7-sums across lanes: w[t] = sum v[t..t+6]
            float w0, w1, w2, w3, w4;
            {
                float a, b;
                a  = sx  + __shfl_down_sync(0xffffffffu, sx, 1);
                b  = a   + __shfl_down_sync(0xffffffffu, a, 2);
                w0 = b   + __shfl_down_sync(0xffffffffu, a, 4)
                         + __shfl_down_sync(0xffffffffu, sx, 6);
                a  = sy  + __shfl_down_sync(0xffffffffu, sy, 1);
                b  = a   + __shfl_down_sync(0xffffffffu, a, 2);
                w1 = b   + __shfl_down_sync(0xffffffffu, a, 4)
                         + __shfl_down_sync(0xffffffffu, sy, 6);
                a  = sxx + __shfl_down_sync(0xffffffffu, sxx, 1);
                b  = a   + __shfl_down_sync(0xffffffffu, a, 2);
                w2 = b   + __shfl_down_sync(0xffffffffu, a, 4)
                         + __shfl_down_sync(0xffffffffu, sxx, 6);
                a  = syy + __shfl_down_sync(0xffffffffu, syy, 1);
                b  = a   + __shfl_down_sync(0xffffffffu, a, 2);
                w3 = b   + __shfl_down_sync(0xffffffffu, a, 4)
                         + __shfl_down_sync(0xffffffffu, syy, 6);
                a  = sxy + __shfl_down_sync(0xffffffffu, sxy, 1);
                b  = a   + __shfl_down_sync(0xffffffffu, a, 2);
                w4 = b   + __shfl_down_sync(0xffffffffu, a, 4)
                         + __shfl_down_sync(0xffffffffu, sxy, 6);
            }

            // SSIM from unnormalized window sums (constants folded):
            // ux=w0*s1 etc.;  A = w2 - w0^2*s1  (49*vx/covn), etc.
            {
                float p01 = w0 * w1;
                float p00 = w0 * w0;
                float p11 = w1 * w1;
                float Axy = fmaf(-p01, s1, w4);
                float A   = fmaf(-p00, s1, w2);
                float B   = fmaf(-p11, s1, w3);
                float n1  = fmaf(k_n1, p01, C1v);          // 2*ux*uy + C1
                float n2  = fmaf(k_c2, Axy, C2v);          // 2*vxy   + C2
                float d1  = fmaf(k_s2, p00 + p11, C1v);    // ux^2+uy^2 + C1
                float d2  = fmaf(k_cv, A + B, C2v);        // vx+vy   + C2
                float num = n1 * n2;
                float den = d1 * d2;
                acc = fmaf(vmask, __fdividef(num, den), acc);
            }
        }
    }

    // deterministic warp reduction
    #pragma unroll
    for (int off = 16; off > 0; off >>= 1)
        acc += __shfl_xor_sync(0xffffffffu, acc, off);
    if (lane == 0) g_partials[W] = acc;
}

#define RED_T 512
__global__ void ssim_reduce_kernel(float* __restrict__ out) {
    __shared__ float red[RED_T];
    const int t = threadIdx.x;
    float a = 0.0f;
    #pragma unroll
    for (int i = t; i < NPART; i += RED_T) a += g_partials[i];
    red[t] = a;
    __syncthreads();
    #pragma unroll
    for (int s = RED_T / 2; s > 0; s >>= 1) {
        if (t < s) red[t] += red[t + s];
        __syncthreads();
    }
    if (t == 0)
        out[0] = red[0] * (1.0f / ((float)NIMG * (float)OUT_W * (float)OUT_H));
}

extern "C" void kernel_launch(void* const* d_in, const int* in_sizes, int n_in,
                              void* d_out, int out_size) {
    const float* pred   = (const float*)d_in[0];
    const float* actual = (const float*)d_in[1];
    float* out = (float*)d_out;

    ssim_warp_kernel<<<NCTA, WARPS_PER_CTA * 32>>>(pred, actual);
    ssim_reduce_kernel<<<1, RED_T>>>(out);
}

// round 4
// speedup vs baseline: 2.3768x; 1.9635x over previous
#include <cuda_runtime.h>

// SSIM, 7x7 VALID box, 128 x 384x384 fp32 pairs -> scalar mean.
//
// v4: quad-column warp strips + packed f32x2 arithmetic.
// Each lane owns 4 consecutive input columns (LDG.128). Vertical 7-row
// sliding sums of {x,y,xx,yy,xy} kept packed (f32x2 per column pair);
// the leaving row is re-loaded from L1 instead of a register ring.
// Horizontal 7-sums via quad decomposition: 4 shuffles/quantity -> 4 outputs.
// SSIM evaluated on packed output pairs (f32x2). Barrier-free.

#define IMG_H 384
#define IMG_W 384
#define OUT_W 378
#define OUT_H 378
#define NIMG  128
#define NSTRIP 4
#define NBAND  6
#define BAND_OUT 63
#define WARPS_PER_CTA 8
#define WARPS_TOTAL (NIMG * NSTRIP * NBAND)      // 3072
#define NCTA (WARPS_TOTAL / WARPS_PER_CTA)       // 384

__device__ float g_partials[WARPS_TOTAL];

typedef unsigned long long u64;
static __device__ __forceinline__ u64 pk2(float lo, float hi) {
    u64 r; asm("mov.b64 %0,{%1,%2};" : "=l"(r) : "f"(lo), "f"(hi)); return r;
}
static __device__ __forceinline__ void upk2(float& lo, float& hi, u64 v) {
    asm("mov.b64 {%0,%1},%2;" : "=f"(lo), "=f"(hi) : "l"(v));
}
static __device__ __forceinline__ u64 add2(u64 a, u64 b) {
    u64 d; asm("add.rn.f32x2 %0,%1,%2;" : "=l"(d) : "l"(a), "l"(b)); return d;
}
static __device__ __forceinline__ u64 mul2(u64 a, u64 b) {
    u64 d; asm("mul.rn.f32x2 %0,%1,%2;" : "=l"(d) : "l"(a), "l"(b)); return d;
}
static __device__ __forceinline__ u64 fma2(u64 a, u64 b, u64 c) {
    u64 d; asm("fma.rn.f32x2 %0,%1,%2,%3;" : "=l"(d) : "l"(a), "l"(b), "l"(c)); return d;
}
static __device__ __forceinline__ u64 neg2(u64 a) {  // sign-flip both halves (LOP, alu pipe)
    return a ^ 0x8000000080000000ULL;
}

// horizontal quad 7-sum: inputs (v0..v3) packed as q01,q23 per lane;
// outputs W0..W3 for output columns 4l+0..4l+3.
#define HQUAD(q01, q23, Wlo, Whi)                                        \
    {                                                                    \
        float v0, v1, v2, v3;                                            \
        upk2(v0, v1, q01); upk2(v2, v3, q23);                            \
        float ab  = v0 + v1;                                             \
        float abc = ab + v2;                                             \
        float q   = abc + v3;                                            \
        float bcd = q - v0;                                              \
        float cd  = q - ab;                                              \
        float dd  = q - abc;                                             \
        float s_abc = __shfl_down_sync(0xffffffffu, abc, 1);             \
        float s_q1  = __shfl_down_sync(0xffffffffu, q,   1);             \
        float s_a2  = __shfl_down_sync(0xffffffffu, v0,  2);             \
        float s_ab2 = __shfl_down_sync(0xffffffffu, ab,  2);             \
        float W0 = q   + s_abc;                                          \
        float W1 = bcd + s_q1;                                           \
        float W2 = cd  + (s_q1 + s_a2);                                  \
        float W3 = dd  + (s_q1 + s_ab2);                                 \
        Wlo = pk2(W0, W1); Whi = pk2(W2, W3);                            \
    }

__global__ __launch_bounds__(WARPS_PER_CTA * 32)
void ssim_v4_kernel(const float* __restrict__ pred,
                    const float* __restrict__ actual) {
    const int gtid = blockIdx.x * blockDim.x + threadIdx.x;
    const int W    = gtid >> 5;
    const int lane = gtid & 31;

    const int img   = W / (NSTRIP * NBAND);
    const int rem   = W - img * (NSTRIP * NBAND);
    const int band  = rem / NSTRIP;
    const int strip = rem - band * NSTRIP;

    // strips: [0,96) [96,192) [192,284) [284,378); bases multiple of 4
    int base = strip * 96;          if (strip == 3) base = 284;
    int send = base + 96;           if (strip == 2) send = 284;
    if (strip == 3) send = 378;

    int cs = base + 4 * lane;       // first input column of this lane
    if (cs > IMG_W - 4) cs = IMG_W - 4;   // clamp (strip 3, lanes >= 25)

    const int r0 = band * BAND_OUT;       // first output row of this band

    const float* __restrict__ xp = pred   + (size_t)img * IMG_H * IMG_W;
    const float* __restrict__ yp = actual + (size_t)img * IMG_H * IMG_W;

    // output masks for the lane's 4 output columns
    const int oc = base + 4 * lane;
    const float m0 = (oc + 0 < send) ? 1.f : 0.f;
    const float m1 = (oc + 1 < send) ? 1.f : 0.f;
    const float m2 = (oc + 2 < send) ? 1.f : 0.f;
    const float m3 = (oc + 3 < send) ? 1.f : 0.f;

    // packed vertical sliding sums
    u64 X01 = 0, X23 = 0, Y01 = 0, Y23 = 0;
    u64 XX01 = 0, XX23 = 0, YY01 = 0, YY23 = 0, XY01 = 0, XY23 = 0;

    // ---- prologue: input rows r0 .. r0+5 ----
    #pragma unroll 1
    for (int k = 0; k < 6; ++k) {
        float4 a = *(const float4*)(xp + (size_t)(r0 + k) * IMG_W + cs);
        float4 b = *(const float4*)(yp + (size_t)(r0 + k) * IMG_W + cs);
        u64 ax01 = pk2(a.x, a.y), ax23 = pk2(a.z, a.w);
        u64 ay01 = pk2(b.x, b.y), ay23 = pk2(b.z, b.w);
        X01 = add2(X01, ax01);  X23 = add2(X23, ax23);
        Y01 = add2(Y01, ay01);  Y23 = add2(Y23, ay23);
        XX01 = fma2(ax01, ax01, XX01);  XX23 = fma2(ax23, ax23, XX23);
        YY01 = fma2(ay01, ay01, YY01);  YY23 = fma2(ay23, ay23, YY23);
        XY01 = fma2(ax01, ay01, XY01);  XY23 = fma2(ax23, ay23, XY23);
    }

    // prefetch input row r0+6
    float4 pfx = *(const float4*)(xp + (size_t)(r0 + 6) * IMG_W + cs);
    float4 pfy = *(const float4*)(yp + (size_t)(r0 + 6) * IMG_W + cs);

    // SSIM constants (folded; identical math to the verified v3)
    const float s1   = 1.0f / 49.0f;
    const float covn = 49.0f / 48.0f;
    const u64 c_ns1 = pk2(-s1, -s1);
    const u64 c_kn1 = pk2(2.f * s1 * s1, 2.f * s1 * s1);
    const u64 c_ks2 = pk2(s1 * s1, s1 * s1);
    const u64 c_kcv = pk2(covn * s1, covn * s1);
    const u64 c_kc2 = pk2(2.f * covn * s1, 2.f * covn * s1);
    const u64 c_C1  = pk2(1e-4f, 1e-4f);
    const u64 c_C2  = pk2(9e-4f, 9e-4f);

    float acc = 0.0f;

    #pragma unroll 1
    for (int r = 0; r < BAND_OUT; ++r) {
        // ---- admit prefetched row (input r0+r+6) ----
        {
            u64 ax01 = pk2(pfx.x, pfx.y), ax23 = pk2(pfx.z, pfx.w);
            u64 ay01 = pk2(pfy.x, pfy.y), ay23 = pk2(pfy.z, pfy.w);
            X01 = add2(X01, ax01);  X23 = add2(X23, ax23);
            Y01 = add2(Y01, ay01);  Y23 = add2(Y23, ay23);
            XX01 = fma2(ax01, ax01, XX01);  XX23 = fma2(ax23, ax23, XX23);
            YY01 = fma2(ay01, ay01, YY01);  YY23 = fma2(ay23, ay23, YY23);
            XY01 = fma2(ax01, ay01, XY01);  XY23 = fma2(ax23, ay23, XY23);
        }
        // ---- prefetch next new row (clamped; garbage unused past the end) ----
        {
            int nr = r0 + r + 7;
            if (nr > IMG_H - 1) nr = IMG_H - 1;
            pfx = *(const float4*)(xp + (size_t)nr * IMG_W + cs);
            pfy = *(const float4*)(yp + (size_t)nr * IMG_W + cs);
        }

        // ---- horizontal quad sums for the 5 quantities ----
        u64 WXl, WXh, WYl, WYh, WXXl, WXXh, WYYl, WYYh, WXYl, WXYh;
        HQUAD(X01,  X23,  WXl,  WXh);
        HQUAD(Y01,  Y23,  WYl,  WYh);
        HQUAD(XX01, XX23, WXXl, WXXh);
        HQUAD(YY01, YY23, WYYl, WYYh);
        HQUAD(XY01, XY23, WXYl, WXYh);

        // ---- SSIM on packed output pairs ----
        {
            // pair (out 4l+0, 4l+1)
            u64 p01 = mul2(WXl, WYl);
            u64 p00 = mul2(WXl, WXl);
            u64 p11 = mul2(WYl, WYl);
            u64 Axy = fma2(p01, c_ns1, WXYl);
            u64 A   = fma2(p00, c_ns1, WXXl);
            u64 B   = fma2(p11, c_ns1, WYYl);
            u64 n1  = fma2(p01, c_kn1, c_C1);
            u64 n2  = fma2(Axy, c_kc2, c_C2);
            u64 d1  = fma2(add2(p00, p11), c_ks2, c_C1);
            u64 d2  = fma2(add2(A, B), c_kcv, c_C2);
            u64 num = mul2(n1, n2);
            u64 den = mul2(d1, d2);
            float na, nb, da, db;
            upk2(na, nb, num); upk2(da, db, den);
            acc = fmaf(m0, __fdividef(na, da), acc);
            acc = fmaf(m1, __fdividef(nb, db), acc);
        }
        {
            // pair (out 4l+2, 4l+3)
            u64 p01 = mul2(WXh, WYh);
            u64 p00 = mul2(WXh, WXh);
            u64 p11 = mul2(WYh, WYh);
            u64 Axy = fma2(p01, c_ns1, WXYh);
            u64 A   = fma2(p00, c_ns1, WXXh);
            u64 B   = fma2(p11, c_ns1, WYYh);
            u64 n1  = fma2(p01, c_kn1, c_C1);
            u64 n2  = fma2(Axy, c_kc2, c_C2);
            u64 d1  = fma2(add2(p00, p11), c_ks2, c_C1);
            u64 d2  = fma2(add2(A, B), c_kcv, c_C2);
            u64 num = mul2(n1, n2);
            u64 den = mul2(d1, d2);
            float na, nb, da, db;
            upk2(na, nb, num); upk2(da, db, den);
            acc = fmaf(m2, __fdividef(na, da), acc);
            acc = fmaf(m3, __fdividef(nb, db), acc);
        }

        // ---- retire leaving row (input r0+r): reload from L1 and subtract ----
        {
            float4 a = *(const float4*)(xp + (size_t)(r0 + r) * IMG_W + cs);
            float4 b = *(const float4*)(yp + (size_t)(r0 + r) * IMG_W + cs);
            u64 ox01 = pk2(a.x, a.y), ox23 = pk2(a.z, a.w);
            u64 oy01 = pk2(b.x, b.y), oy23 = pk2(b.z, b.w);
            u64 nx01 = neg2(ox01), nx23 = neg2(ox23);
            u64 ny01 = neg2(oy01), ny23 = neg2(oy23);
            X01 = add2(X01, nx01);  X23 = add2(X23, nx23);
            Y01 = add2(Y01, ny01);  Y23 = add2(Y23, ny23);
            XX01 = fma2(ox01, nx01, XX01);  XX23 = fma2(ox23, nx23, XX23);
            YY01 = fma2(oy01, ny01, YY01);  YY23 = fma2(oy23, ny23, YY23);
            XY01 = fma2(ox01, ny01, XY01);  XY23 = fma2(ox23, ny23, XY23);
        }
    }

    // deterministic warp reduction
    #pragma unroll
    for (int off = 16; off > 0; off >>= 1)
        acc += __shfl_xor_sync(0xffffffffu, acc, off);
    if (lane == 0) g_partials[W] = acc;
}

#define RED_T 512
__global__ void ssim_reduce_kernel(float* __restrict__ out) {
    __shared__ float red[RED_T];
    const int t = threadIdx.x;
    float a = 0.0f;
    #pragma unroll 1
    for (int i = t; i < WARPS_TOTAL; i += RED_T) a += g_partials[i];
    red[t] = a;
    __syncthreads();
    #pragma unroll
    for (int s = RED_T / 2; s > 0; s >>= 1) {
        if (t < s) red[t] += red[t + s];
        __syncthreads();
    }
    if (t == 0)
        out[0] = red[0] * (1.0f / ((float)NIMG * (float)OUT_W * (float)OUT_H));
}

extern "C" void kernel_launch(void* const* d_in, const int* in_sizes, int n_in,
                              void* d_out, int out_size) {
    const float* pred   = (const float*)d_in[0];
    const float* actual = (const float*)d_in[1];
    float* out = (float*)d_out;

    ssim_v4_kernel<<<NCTA, WARPS_PER_CTA * 32>>>(pred, actual);
    ssim_reduce_kernel<<<1, RED_T>>>(out);
}